// round 12
// baseline (speedup 1.0000x reference)
#include <cuda_runtime.h>
#include <math.h>

#define BATCH  128
#define KK     512
#define NSL    8      // i-slices of 64 rows (K2 paths)
#define SLR    64
#define NSL1   16     // i-slices of 32 rows (K1: Q1 colsum, full wave)
#define SLR1   32
#define TPB    128    // thread owns 4 columns (float4)
#define JSPL   4      // j-chunks in k_final

#define LOGK 6.2383246250395077632f   // log(512)

// Scratch (__device__ globals). Fits in L2; streaming input loads use __ldcs
// (evict-first) so these stay resident.
__device__ float g_Ep0[NSL  * BATCH * KK];  // partial col-sums of exp(Q0) (2 MB)
__device__ float g_Ep1[NSL1 * BATCH * KK];  // partial col-sums of exp(Q1) (4 MB)
__device__ float g_mmp[NSL  * BATCH * KK];  // partial mm sums (2 MB)
__device__ float g_sp[BATCH * JSPL];        // per-(b,chunk) t partial sums
__device__ unsigned int g_tickF;            // zero-init; last block resets

__device__ __forceinline__ float4 ldcs4(const float4* p) { return __ldcs(p); }

// ---------------------------------------------------------------------------
// Kernel 1: partial column sums of exp(Q1) (E1 partials for ew).
// grid = (NSL1, BATCH) = 2048 blocks (one full wave at 14 blocks/SM),
// block = 128, 32 rows/block, 4xfloat4 in flight — the proven 81%-DRAM shape.
// ---------------------------------------------------------------------------
__global__ void __launch_bounds__(TPB, 14) k_colsum_q1(const float* __restrict__ Q1)
{
    const int slice = blockIdx.x;
    const int b     = blockIdx.y;
    const int t     = threadIdx.x;

    const float4* p = (const float4*)(Q1 + (size_t)b * KK * KK
                                         + (size_t)(slice * SLR1) * KK) + t;
    const int rs = KK / 4;

    float sx = 0.f, sy = 0.f, sz = 0.f, sw = 0.f;
#pragma unroll
    for (int i = 0; i < SLR1; i += 4) {
        float4 a0 = ldcs4(p + (i + 0) * rs);
        float4 a1 = ldcs4(p + (i + 1) * rs);
        float4 a2 = ldcs4(p + (i + 2) * rs);
        float4 a3 = ldcs4(p + (i + 3) * rs);
        sx += __expf(a0.x) + __expf(a1.x) + __expf(a2.x) + __expf(a3.x);
        sy += __expf(a0.y) + __expf(a1.y) + __expf(a2.y) + __expf(a3.y);
        sz += __expf(a0.z) + __expf(a1.z) + __expf(a2.z) + __expf(a3.z);
        sw += __expf(a0.w) + __expf(a1.w) + __expf(a2.w) + __expf(a3.w);
    }
    ((float4*)(g_Ep1 + ((size_t)slice * BATCH + b) * KK))[t] =
        make_float4(sx, sy, sz, sw);
}

// ---------------------------------------------------------------------------
// Kernel 2 (heterogeneous, one wave): grid = (2*NSL, BATCH) = 2048 blocks.
//   blockIdx.x <  NSL : mid-path  — mmp[b,j] partial over P1 slice, using
//                       ew built inline from L2-hot g_Ep1 + P0.
//   blockIdx.x >= NSL : colsum-path over the matching Q0 slice.
// __launch_bounds__(128, 14) keeps regs <= 36 -> one wave.
// ---------------------------------------------------------------------------
__global__ void __launch_bounds__(TPB, 14) k_mid_q0(const float* __restrict__ P0,
                                                    const float* __restrict__ P1,
                                                    const float* __restrict__ Q0)
{
    const int b = blockIdx.y;
    const int t = threadIdx.x;
    const int rs = KK / 4;

    if (blockIdx.x < NSL) {
        // ----- mid path: P1 slice -----
        const int slice = blockIdx.x;
        const int i0    = slice * SLR;

        __shared__ float ew[SLR];
        if (t < SLR) {
            const int i = i0 + t;
            float e1 = g_Ep1[((size_t)0 * BATCH + b) * KK + i];
#pragma unroll
            for (int s = 1; s < NSL1; s++)
                e1 += g_Ep1[((size_t)s * BATCH + b) * KK + i];
            ew[t] = __expf(P0[b * KK + i]) * (float)KK / e1;
        }
        __syncthreads();

        const float4* p = (const float4*)(P1 + (size_t)b * KK * KK
                                             + (size_t)i0 * KK) + t;

        float sx = 0.f, sy = 0.f, sz = 0.f, sw = 0.f;
#pragma unroll
        for (int i = 0; i < SLR; i += 4) {
            float4 a0 = ldcs4(p + (i + 0) * rs);
            float4 a1 = ldcs4(p + (i + 1) * rs);
            float4 a2 = ldcs4(p + (i + 2) * rs);
            float4 a3 = ldcs4(p + (i + 3) * rs);
            float w0 = ew[i + 0], w1 = ew[i + 1], w2 = ew[i + 2], w3 = ew[i + 3];
            sx += w0 * __expf(a0.x) + w1 * __expf(a1.x)
                + w2 * __expf(a2.x) + w3 * __expf(a3.x);
            sy += w0 * __expf(a0.y) + w1 * __expf(a1.y)
                + w2 * __expf(a2.y) + w3 * __expf(a3.y);
            sz += w0 * __expf(a0.z) + w1 * __expf(a1.z)
                + w2 * __expf(a2.z) + w3 * __expf(a3.z);
            sw += w0 * __expf(a0.w) + w1 * __expf(a1.w)
                + w2 * __expf(a2.w) + w3 * __expf(a3.w);
        }
        ((float4*)(g_mmp + ((size_t)slice * BATCH + b) * KK))[t] =
            make_float4(sx, sy, sz, sw);
    } else {
        // ----- colsum path: Q0 slice -----
        const int slice = blockIdx.x - NSL;

        const float4* p = (const float4*)(Q0 + (size_t)b * KK * KK
                                             + (size_t)(slice * SLR) * KK) + t;

        float sx = 0.f, sy = 0.f, sz = 0.f, sw = 0.f;
#pragma unroll
        for (int i = 0; i < SLR; i += 4) {
            float4 a0 = ldcs4(p + (i + 0) * rs);
            float4 a1 = ldcs4(p + (i + 1) * rs);
            float4 a2 = ldcs4(p + (i + 2) * rs);
            float4 a3 = ldcs4(p + (i + 3) * rs);
            sx += __expf(a0.x) + __expf(a1.x) + __expf(a2.x) + __expf(a3.x);
            sy += __expf(a0.y) + __expf(a1.y) + __expf(a2.y) + __expf(a3.y);
            sz += __expf(a0.z) + __expf(a1.z) + __expf(a2.z) + __expf(a3.z);
            sw += __expf(a0.w) + __expf(a1.w) + __expf(a2.w) + __expf(a3.w);
        }
        ((float4*)(g_Ep0 + ((size_t)slice * BATCH + b) * KK))[t] =
            make_float4(sx, sy, sz, sw);
    }
}

// ---------------------------------------------------------------------------
// Kernel 3: t partials + deterministic finish.
// grid = (JSPL, BATCH) = 512 blocks, block = 128.
// ---------------------------------------------------------------------------
__global__ void __launch_bounds__(TPB) k_final(const float* __restrict__ P2,
                                               float* __restrict__ out)
{
    const int js = blockIdx.x;
    const int b  = blockIdx.y;
    const int t  = threadIdx.x;
    const int j  = js * TPB + t;

    float m = 0.f, e0 = 0.f;
#pragma unroll
    for (int s = 0; s < NSL; s++) {
        m  += g_mmp[((size_t)s * BATCH + b) * KK + j];
        e0 += g_Ep0[((size_t)s * BATCH + b) * KK + j];
    }
    float acc = m / e0 * __expf(P2[b * KK + j]);

#pragma unroll
    for (int o = 16; o; o >>= 1)
        acc += __shfl_down_sync(0xFFFFFFFFu, acc, o);

    __shared__ float red[4];
    if ((t & 31) == 0) red[t >> 5] = acc;
    __syncthreads();

    __shared__ bool amLast;
    if (t == 0) {
        g_sp[b * JSPL + js] = (red[0] + red[1]) + (red[2] + red[3]);
        __threadfence();
        amLast = (atomicAdd(&g_tickF, 1u) == BATCH * JSPL - 1);
    }
    __syncthreads();

    if (amLast) {
        __shared__ float sm[BATCH];
        float s = (g_sp[t * JSPL + 0] + g_sp[t * JSPL + 1])
                + (g_sp[t * JSPL + 2] + g_sp[t * JSPL + 3]);
        sm[t] = LOGK - logf(s);
        __syncthreads();
#pragma unroll
        for (int off = BATCH / 2; off > 0; off >>= 1) {
            if (t < off) sm[t] += sm[t + off];
            __syncthreads();
        }
        if (t == 0) {
            out[0] = sm[0];
            g_tickF = 0;   // reset for graph replay
        }
    }
}

// ---------------------------------------------------------------------------
extern "C" void kernel_launch(void* const* d_in, const int* in_sizes, int n_in,
                              void* d_out, int out_size)
{
    const float* Q0 = (const float*)d_in[0];  // logQ0 [B,K,K]
    const float* Q1 = (const float*)d_in[1];  // logQ1 [B,K,K]
    const float* P0 = (const float*)d_in[2];  // logP0 [B,1,K]
    const float* P1 = (const float*)d_in[3];  // logP1 [B,K,K]
    const float* P2 = (const float*)d_in[4];  // logP2 [B,K,1]

    dim3 g1(NSL1, BATCH);
    k_colsum_q1<<<g1, TPB>>>(Q1);

    dim3 g2(2 * NSL, BATCH);
    k_mid_q0<<<g2, TPB>>>(P0, P1, Q0);

    dim3 g3(JSPL, BATCH);
    k_final<<<g3, TPB>>>(P2, (float*)d_out);
}